// round 10
// baseline (speedup 1.0000x reference)
#include <cuda_runtime.h>
#include <cstdint>

#define T_LEN   32768
#define NROWS   1024
#define IT      32                      // items per lane per chunk
#define CELEMS  (32 * IT)               // 1024 elements per chunk
#define NCHUNK  (T_LEN / CELEMS)        // 32 chunks per row
#define STAGES  4
#define F4C     256                     // float4 per tensor per chunk
#define STAGE_F4 (2 * F4C)              // P + Q per stage (8 KB)
#define SMEM_F4  (STAGES * STAGE_F4)    // 2048 float4 = 32 KB

__device__ double g_partial[NROWS];
__device__ unsigned int g_count;

__device__ __forceinline__ void cp16(uint32_t dst, const float4* src) {
    asm volatile("cp.async.cg.shared.global [%0], [%1], 16;" :: "r"(dst), "l"(src));
}
__device__ __forceinline__ void cp_commit() {
    asm volatile("cp.async.commit_group;" ::: "memory");
}
template <int N>
__device__ __forceinline__ void cp_wait() {
    asm volatile("cp.async.wait_group %0;" :: "n"(N) : "memory");
}
__device__ __forceinline__ int swz(int v) { return v ^ ((v >> 3) & 7); }

__global__ void __launch_bounds__(32, 7)
wass_kernel(const float* __restrict__ yp, const float* __restrict__ yt,
            float* __restrict__ out) {
    __shared__ float4 smem[SMEM_F4];
    __shared__ bool is_last;

    const int lane = threadIdx.x;
    const int row  = blockIdx.x;

    const float4* __restrict__ p4 = (const float4*)(yp + (long)row * T_LEN);
    const float4* __restrict__ t4 = (const float4*)(yt + (long)row * T_LEN);
    const uint32_t sbase = (uint32_t)__cvta_generic_to_shared(smem);

    // Issue one stage (one commit group): 8 float4 per tensor per lane.
    auto issue = [&](int stage, int chunk) {
        const int vbase = chunk * F4C;
        #pragma unroll
        for (int i = 0; i < 8; i++) {
            int v  = i * 32 + lane;
            int sw = swz(v);
            cp16(sbase + (uint32_t)(stage * STAGE_F4 + sw) * 16u,       p4 + vbase + v);
            cp16(sbase + (uint32_t)(stage * STAGE_F4 + F4C + sw) * 16u, t4 + vbase + v);
        }
        cp_commit();
    };

    // Prologue: chunks 0..2 into stages 0..2 (3 groups / 24KB outstanding).
    issue(0, 0); issue(1, 1); issue(2, 2);

    double dacc = 0.0;
    float  carry = 0.0f;

    for (int f = 0; f < NCHUNK; f++) {
        const int s = f & (STAGES - 1);

        cp_wait<STAGES - 2>();     // chunk f's group complete
        __syncwarp();

        // Refill the stage consumed last iteration with chunk f+3 (race-free).
        const int nc = f + STAGES - 1;
        if (nc < NCHUNK) issue((s + STAGES - 1) & (STAGES - 1), nc);
        else             cp_commit();

        // Consume stage s: lane reads 32 contiguous elements (8 float4).
        float d[IT];
        #pragma unroll
        for (int j = 0; j < 8; j++) {
            int v  = lane * 8 + j;
            int sw = swz(v);
            float4 Pj = smem[s * STAGE_F4 + sw];
            float4 Qj = smem[s * STAGE_F4 + F4C + sw];
            d[4*j+0] = Pj.x - Qj.x;
            d[4*j+1] = Pj.y - Qj.y;
            d[4*j+2] = Pj.z - Qj.z;
            d[4*j+3] = Pj.w - Qj.w;
        }

        // Segment total via tree (depth 5) — feeds the scan ASAP.
        float t2[16], t4a[8], t8[4], t16[2];
        #pragma unroll
        for (int j = 0; j < 16; j++) t2[j] = d[2*j] + d[2*j+1];
        #pragma unroll
        for (int j = 0; j < 8; j++)  t4a[j] = t2[2*j] + t2[2*j+1];
        #pragma unroll
        for (int j = 0; j < 4; j++)  t8[j] = t4a[2*j] + t4a[2*j+1];
        t16[0] = t8[0] + t8[1];  t16[1] = t8[2] + t8[3];
        float seg = t16[0] + t16[1];

        // Warp inclusive scan of segment sums (critical carry chain).
        float inc = seg;
        #pragma unroll
        for (int o = 1; o < 32; o <<= 1) {
            float y = __shfl_up_sync(0xffffffffu, inc, o);
            if (lane >= o) inc += y;
        }
        float total = __shfl_sync(0xffffffffu, inc, 31);

        // Per-lane inclusive prefix (overlaps with the shfl chain above).
        float pr[IT];
        pr[0] = d[0];
        #pragma unroll
        for (int k = 1; k < IT; k++) pr[k] = pr[k-1] + d[k];

        float base = carry + (inc - seg);
        carry += total;

        // Weighted |cumsum| accumulation, 4 independent FMA chains.
        const int idx0 = f * CELEMS + lane * IT;
        const float w0 = (float)(T_LEN - idx0);
        float a0 = 0.0f, a1 = 0.0f, a2 = 0.0f, a3 = 0.0f;
        #pragma unroll
        for (int k = 0; k < IT; k += 4) {
            a0 = fmaf(fabsf(base + pr[k]),   w0 - (float)k,       a0);
            a1 = fmaf(fabsf(base + pr[k+1]), w0 - (float)(k + 1), a1);
            a2 = fmaf(fabsf(base + pr[k+2]), w0 - (float)(k + 2), a2);
            a3 = fmaf(fabsf(base + pr[k+3]), w0 - (float)(k + 3), a3);
        }
        dacc += (double)((a0 + a1) + (a2 + a3));
    }

    // Warp reduction of dacc (deterministic).
    #pragma unroll
    for (int o = 16; o > 0; o >>= 1)
        dacc += __shfl_down_sync(0xffffffffu, dacc, o);
    if (lane == 0) {
        g_partial[row] = dacc;
        __threadfence();
        unsigned int prev = atomicAdd(&g_count, 1u);
        is_last = (prev == (unsigned int)(gridDim.x - 1));
    }
    __syncwarp();
    int last = __shfl_sync(0xffffffffu, (int)is_last, 0);

    // Last block: final deterministic reduce of 1024 partials with one warp.
    if (last) {
        if (lane == 0) g_count = 0;   // reset for graph replay
        double v = 0.0;
        #pragma unroll
        for (int j = 0; j < NROWS / 32; j++)
            v += g_partial[lane * (NROWS / 32) + j];
        #pragma unroll
        for (int o = 16; o > 0; o >>= 1)
            v += __shfl_down_sync(0xffffffffu, v, o);
        if (lane == 0) {
            double tc = (double)T_LEN * 16.0;            // T*C
            double scale = 2.0 / (tc * (tc + 1.0));
            out[0] = (float)((v / 64.0) * scale);        // mean over B=64
        }
    }
}

extern "C" void kernel_launch(void* const* d_in, const int* in_sizes, int n_in,
                              void* d_out, int out_size) {
    (void)in_sizes; (void)n_in; (void)out_size;
    const float* y_pred = (const float*)d_in[0];
    const float* y_true = (const float*)d_in[1];
    float* out = (float*)d_out;
    wass_kernel<<<NROWS, 32>>>(y_pred, y_true, out);
}

// round 11
// speedup vs baseline: 1.2094x; 1.2094x over previous
#include <cuda_runtime.h>
#include <cstdint>

#define T_LEN   32768
#define NROWS   1024
#define IT      16                      // items per lane per chunk
#define CELEMS  (32 * IT)               // 512 elements per chunk
#define NCHUNK  (T_LEN / CELEMS)        // 64 chunks per row
#define STAGES  4
#define F4C     128                     // float4 per tensor per chunk
#define STAGE_F4 (2 * F4C)              // P + Q per stage
#define SMEM_F4  (STAGES * STAGE_F4)    // 1024 float4 = 16 KB

__device__ double g_partial[NROWS];
__device__ unsigned int g_count;

__device__ __forceinline__ void cp16(uint32_t dst, const float4* src) {
    asm volatile("cp.async.cg.shared.global [%0], [%1], 16;" :: "r"(dst), "l"(src));
}
__device__ __forceinline__ void cp_commit() {
    asm volatile("cp.async.commit_group;" ::: "memory");
}
template <int N>
__device__ __forceinline__ void cp_wait() {
    asm volatile("cp.async.wait_group %0;" :: "n"(N) : "memory");
}
__device__ __forceinline__ int swz(int v) { return v ^ ((v >> 3) & 7); }

__global__ void __launch_bounds__(32, 8)
wass_kernel(const float* __restrict__ yp, const float* __restrict__ yt,
            float* __restrict__ out) {
    __shared__ float4 smem[SMEM_F4];
    __shared__ bool is_last;

    const int lane = threadIdx.x;
    const int row  = blockIdx.x;

    const float4* __restrict__ p4 = (const float4*)(yp + (long)row * T_LEN);
    const float4* __restrict__ t4 = (const float4*)(yt + (long)row * T_LEN);
    const uint32_t sbase = (uint32_t)__cvta_generic_to_shared(smem);

    // Issue one stage (one commit group): 4 float4 per tensor per lane.
    auto issue = [&](int stage, int chunk) {
        const int vbase = chunk * F4C;
        #pragma unroll
        for (int i = 0; i < 4; i++) {
            int v  = i * 32 + lane;
            int sw = swz(v);
            cp16(sbase + (uint32_t)(stage * STAGE_F4 + sw) * 16u,       p4 + vbase + v);
            cp16(sbase + (uint32_t)(stage * STAGE_F4 + F4C + sw) * 16u, t4 + vbase + v);
        }
        cp_commit();
    };

    // Prologue: chunks 0..2 into stages 0..2 (3 groups pending).
    issue(0, 0); issue(1, 1); issue(2, 2);

    double dacc = 0.0;
    float  carry = 0.0f;

    // Pipelined compute state: previous chunk's prefixes + base + weight.
    float pr_prev[IT];
    float base_prev = 0.0f, w_prev = 0.0f;

    #pragma unroll 4
    for (int f = 0; f < NCHUNK; f++) {
        const int s = f & (STAGES - 1);

        cp_wait<STAGES - 2>();     // chunk f's group complete
        __syncwarp();

        // Refill the stage consumed last iteration with chunk f+3 (race-free).
        const int nc = f + STAGES - 1;
        if (nc < NCHUNK) issue((s + STAGES - 1) & (STAGES - 1), nc);
        else             cp_commit();

        // Consume stage s: lane reads 16 contiguous elements (4 float4).
        float d[IT];
        #pragma unroll
        for (int j = 0; j < 4; j++) {
            int v  = lane * 4 + j;
            int sw = swz(v);
            float4 Pj = smem[s * STAGE_F4 + sw];
            float4 Qj = smem[s * STAGE_F4 + F4C + sw];
            d[4*j+0] = Pj.x - Qj.x;
            d[4*j+1] = Pj.y - Qj.y;
            d[4*j+2] = Pj.z - Qj.z;
            d[4*j+3] = Pj.w - Qj.w;
        }

        // Segment total via depth-4 tree — gets the scan started ASAP.
        float t2[8], t4a[4], t8[2];
        #pragma unroll
        for (int j = 0; j < 8; j++) t2[j] = d[2*j] + d[2*j+1];
        #pragma unroll
        for (int j = 0; j < 4; j++) t4a[j] = t2[2*j] + t2[2*j+1];
        t8[0] = t4a[0] + t4a[1];  t8[1] = t4a[2] + t4a[3];
        float seg = t8[0] + t8[1];

        // Warp inclusive scan (5 dependent shfls — the latency shadow).
        float inc = seg;
        #pragma unroll
        for (int o = 1; o < 32; o <<= 1) {
            float y = __shfl_up_sync(0xffffffffu, inc, o);
            if (lane >= o) inc += y;
        }
        float total = __shfl_sync(0xffffffffu, inc, 31);

        // --- Fill the scan shadow with independent work: ---
        // (1) per-lane prefix chain for chunk f
        float pr[IT];
        pr[0] = d[0];
        #pragma unroll
        for (int k = 1; k < IT; k++) pr[k] = pr[k-1] + d[k];

        // (2) weighted FMA loop for chunk f-1 (registers only, independent of scan f)
        if (f > 0) {
            float a0 = 0.0f, a1 = 0.0f;
            #pragma unroll
            for (int k = 0; k < IT; k += 2) {
                a0 = fmaf(fabsf(base_prev + pr_prev[k]),   w_prev - (float)k,       a0);
                a1 = fmaf(fabsf(base_prev + pr_prev[k+1]), w_prev - (float)(k + 1), a1);
            }
            dacc += (double)(a0 + a1);
        }

        // Carry update (cheap add chain across chunks).
        float base = carry + (inc - seg);
        carry += total;

        // Rotate pipeline state.
        #pragma unroll
        for (int k = 0; k < IT; k++) pr_prev[k] = pr[k];
        base_prev = base;
        w_prev = (float)(T_LEN - (f * CELEMS + lane * IT));
    }

    // Epilogue: FMA for the final chunk.
    {
        float a0 = 0.0f, a1 = 0.0f;
        #pragma unroll
        for (int k = 0; k < IT; k += 2) {
            a0 = fmaf(fabsf(base_prev + pr_prev[k]),   w_prev - (float)k,       a0);
            a1 = fmaf(fabsf(base_prev + pr_prev[k+1]), w_prev - (float)(k + 1), a1);
        }
        dacc += (double)(a0 + a1);
    }

    // Warp reduction of dacc (deterministic).
    #pragma unroll
    for (int o = 16; o > 0; o >>= 1)
        dacc += __shfl_down_sync(0xffffffffu, dacc, o);
    if (lane == 0) {
        g_partial[row] = dacc;
        __threadfence();
        unsigned int prev = atomicAdd(&g_count, 1u);
        is_last = (prev == (unsigned int)(gridDim.x - 1));
    }
    __syncwarp();
    int last = __shfl_sync(0xffffffffu, (int)is_last, 0);

    // Last block: final deterministic reduce of 1024 partials with one warp.
    if (last) {
        if (lane == 0) g_count = 0;   // reset for graph replay
        double v = 0.0;
        #pragma unroll
        for (int j = 0; j < NROWS / 32; j++)
            v += g_partial[lane * (NROWS / 32) + j];
        #pragma unroll
        for (int o = 16; o > 0; o >>= 1)
            v += __shfl_down_sync(0xffffffffu, v, o);
        if (lane == 0) {
            double tc = (double)T_LEN * 16.0;            // T*C
            double scale = 2.0 / (tc * (tc + 1.0));
            out[0] = (float)((v / 64.0) * scale);        // mean over B=64
        }
    }
}

extern "C" void kernel_launch(void* const* d_in, const int* in_sizes, int n_in,
                              void* d_out, int out_size) {
    (void)in_sizes; (void)n_in; (void)out_size;
    const float* y_pred = (const float*)d_in[0];
    const float* y_true = (const float*)d_in[1];
    float* out = (float*)d_out;
    wass_kernel<<<NROWS, 32>>>(y_pred, y_true, out);
}

// round 12
// speedup vs baseline: 1.2151x; 1.0047x over previous
#include <cuda_runtime.h>
#include <cstdint>

#define T_LEN   32768
#define NROWS   1024
#define CELEMS  512                     // elements per chunk
#define NCHUNK  (T_LEN / CELEMS)        // 64 chunks per row
#define STAGES  4
#define STAGE_F4 256                    // 128 f4 P + 128 f4 Q = 4 KB per stage

__device__ double g_partial[NROWS];
__device__ unsigned int g_count;

__device__ __forceinline__ void mbar_init(uint32_t m, uint32_t cnt) {
    asm volatile("mbarrier.init.shared::cta.b64 [%0], %1;" :: "r"(m), "r"(cnt) : "memory");
}
__device__ __forceinline__ void mbar_expect_tx(uint32_t m, uint32_t bytes) {
    asm volatile("mbarrier.arrive.expect_tx.shared::cta.b64 _, [%0], %1;"
                 :: "r"(m), "r"(bytes) : "memory");
}
__device__ __forceinline__ void bulk_g2s(uint32_t dst, const void* src, uint32_t bytes, uint32_t m) {
    asm volatile("cp.async.bulk.shared::cta.global.mbarrier::complete_tx::bytes "
                 "[%0], [%1], %2, [%3];"
                 :: "r"(dst), "l"(src), "r"(bytes), "r"(m) : "memory");
}
__device__ __forceinline__ void mbar_wait(uint32_t m, uint32_t phase) {
    uint32_t done;
    asm volatile(
        "{\n\t.reg .pred p;\n\t"
        "mbarrier.try_wait.parity.acquire.cta.shared::cta.b64 p, [%1], %2;\n\t"
        "selp.b32 %0, 1, 0, p;\n\t}"
        : "=r"(done) : "r"(m), "r"(phase) : "memory");
    if (!done) {
        asm volatile(
            "{\n\t.reg .pred P1;\n\t"
            "WL_%=:\n\t"
            "mbarrier.try_wait.parity.acquire.cta.shared::cta.b64 P1, [%0], %1, 0x989680;\n\t"
            "@P1 bra.uni WD_%=;\n\t"
            "bra.uni WL_%=;\n\t"
            "WD_%=:\n\t}"
            :: "r"(m), "r"(phase) : "memory");
    }
}

__global__ void __launch_bounds__(32, 8)
wass_kernel(const float* __restrict__ yp, const float* __restrict__ yt,
            float* __restrict__ out) {
    __shared__ alignas(1024) float4 smem[STAGES * STAGE_F4];   // 16 KB
    __shared__ alignas(8) unsigned long long mbar[STAGES];
    __shared__ bool is_last;

    const int lane = threadIdx.x;
    const int row  = blockIdx.x;

    const float* __restrict__ prow = yp + (long)row * T_LEN;
    const float* __restrict__ trow = yt + (long)row * T_LEN;
    const uint32_t sbase = (uint32_t)__cvta_generic_to_shared(smem);
    const uint32_t mbase = (uint32_t)__cvta_generic_to_shared(mbar);

    if (lane == 0) {
        #pragma unroll
        for (int s = 0; s < STAGES; s++) mbar_init(mbase + s * 8u, 1u);
    }
    __syncwarp();

    // Issue one stage: expect 4KB, two 2KB bulk copies (P then Q). Lane 0 only.
    auto issue = [&](int stage, int chunk) {
        uint32_t m  = mbase + (uint32_t)stage * 8u;
        uint32_t dP = sbase + (uint32_t)stage * 4096u;
        mbar_expect_tx(m, 4096u);
        bulk_g2s(dP,          prow + chunk * CELEMS, 2048u, m);
        bulk_g2s(dP + 2048u,  trow + chunk * CELEMS, 2048u, m);
    };

    // Prologue: chunks 0..2 into stages 0..2.
    if (lane == 0) { issue(0, 0); issue(1, 1); issue(2, 2); }

    double dacc = 0.0;
    float  carry = 0.0f;

    #pragma unroll 4
    for (int f = 0; f < NCHUNK; f++) {
        const int s   = f & (STAGES - 1);
        const int par = (f >> 2) & 1;

        mbar_wait(mbase + (uint32_t)s * 8u, (uint32_t)par);
        __syncwarp();   // all lanes past consumption of stage (s-1) and wait done

        // Refill stage consumed last iteration with chunk f+3 (race-free).
        const int nc = f + STAGES - 1;
        if (nc < NCHUNK && lane == 0) issue((s + STAGES - 1) & (STAGES - 1), nc);

        // Consume: lane owns 4-element runs at stride 128 (conflict-free LDS.128).
        const float4* sp = smem + s * STAGE_F4;         // [0,128): P, [128,256): Q
        float lp[4][4];     // inclusive local prefixes per group j
        float r0, r1, r2, r3;
        {
            #pragma unroll
            for (int j = 0; j < 4; j++) {
                float4 Pj = sp[lane + 32 * j];
                float4 Qj = sp[128 + lane + 32 * j];
                float d0 = Pj.x - Qj.x, d1 = Pj.y - Qj.y;
                float d2 = Pj.z - Qj.z, d3 = Pj.w - Qj.w;
                lp[j][0] = d0;
                lp[j][1] = d0 + d1;
                lp[j][2] = lp[j][1] + d2;
                lp[j][3] = lp[j][2] + d3;
            }
            r0 = lp[0][3]; r1 = lp[1][3]; r2 = lp[2][3]; r3 = lp[3][3];
        }

        // 4 independent warp scans (chains overlap; no serial dependence).
        float i0 = r0, i1 = r1, i2 = r2, i3 = r3;
        #pragma unroll
        for (int o = 1; o < 32; o <<= 1) {
            float y0 = __shfl_up_sync(0xffffffffu, i0, o);
            float y1 = __shfl_up_sync(0xffffffffu, i1, o);
            float y2 = __shfl_up_sync(0xffffffffu, i2, o);
            float y3 = __shfl_up_sync(0xffffffffu, i3, o);
            if (lane >= o) { i0 += y0; i1 += y1; i2 += y2; i3 += y3; }
        }
        float S0 = __shfl_sync(0xffffffffu, i0, 31);
        float S1 = __shfl_sync(0xffffffffu, i1, 31);
        float S2 = __shfl_sync(0xffffffffu, i2, 31);
        float S3 = __shfl_sync(0xffffffffu, i3, 31);

        // Group bases.
        float G0 = carry;
        float G1 = G0 + S0;
        float G2 = G1 + S1;
        float G3 = G2 + S2;
        carry = G3 + S3;

        float b0 = G0 + (i0 - r0);
        float b1 = G1 + (i1 - r1);
        float b2 = G2 + (i2 - r2);
        float b3 = G3 + (i3 - r3);

        // Weighted |cumsum| accumulation: idx = f*512 + 128j + 4*lane + i.
        const float wbase = (float)(T_LEN - (f * CELEMS + 4 * lane));
        float a0 = 0.0f, a1 = 0.0f, a2 = 0.0f, a3 = 0.0f;
        #pragma unroll
        for (int j = 0; j < 4; j++) {
            float bj = (j == 0) ? b0 : (j == 1) ? b1 : (j == 2) ? b2 : b3;
            float wj = wbase - (float)(128 * j);
            a0 = fmaf(fabsf(bj + lp[j][0]), wj,          a0);
            a1 = fmaf(fabsf(bj + lp[j][1]), wj - 1.0f,   a1);
            a2 = fmaf(fabsf(bj + lp[j][2]), wj - 2.0f,   a2);
            a3 = fmaf(fabsf(bj + lp[j][3]), wj - 3.0f,   a3);
        }
        dacc += (double)((a0 + a1) + (a2 + a3));
    }

    // Warp reduction of dacc (deterministic).
    #pragma unroll
    for (int o = 16; o > 0; o >>= 1)
        dacc += __shfl_down_sync(0xffffffffu, dacc, o);
    if (lane == 0) {
        g_partial[row] = dacc;
        __threadfence();
        unsigned int prev = atomicAdd(&g_count, 1u);
        is_last = (prev == (unsigned int)(gridDim.x - 1));
    }
    __syncwarp();
    int last = __shfl_sync(0xffffffffu, (int)is_last, 0);

    // Last block: final deterministic reduce of 1024 partials with one warp.
    if (last) {
        if (lane == 0) g_count = 0;   // reset for graph replay
        double v = 0.0;
        #pragma unroll
        for (int j = 0; j < NROWS / 32; j++)
            v += g_partial[lane * (NROWS / 32) + j];
        #pragma unroll
        for (int o = 16; o > 0; o >>= 1)
            v += __shfl_down_sync(0xffffffffu, v, o);
        if (lane == 0) {
            double tc = (double)T_LEN * 16.0;            // T*C
            double scale = 2.0 / (tc * (tc + 1.0));
            out[0] = (float)((v / 64.0) * scale);        // mean over B=64
        }
    }
}

extern "C" void kernel_launch(void* const* d_in, const int* in_sizes, int n_in,
                              void* d_out, int out_size) {
    (void)in_sizes; (void)n_in; (void)out_size;
    const float* y_pred = (const float*)d_in[0];
    const float* y_true = (const float*)d_in[1];
    float* out = (float*)d_out;
    wass_kernel<<<NROWS, 32>>>(y_pred, y_true, out);
}